// round 7
// baseline (speedup 1.0000x reference)
#include <cuda_runtime.h>
#include <math.h>

#define MM      8
#define AA      48
#define NSPEC   4
#define NPAIRCH 10
#define NSHFR   16
#define RADDIM  (NSPEC * NSHFR)            /* 64  */
#define ANGDIM  (NPAIRCH * 32)             /* 320 */
#define OUTDIM  (RADDIM + ANGDIM)          /* 384 */
#define RCR_F   5.2f
#define RCA_F   3.5f
#define PI_F    3.14159265358979323846f
#define FULLM   0xffffffffu

__global__ __launch_bounds__(32, 1) void aev_kernel(
    const float* __restrict__ coords,   // (M, A, 3)
    const float* __restrict__ EtaR,     // (1,)
    const float* __restrict__ ShfR,     // (16,)
    const float* __restrict__ EtaA,     // (1,)
    const float* __restrict__ Zeta,     // (1,)
    const float* __restrict__ ShfA,     // (4,)
    const float* __restrict__ ShfZ,     // (8,)
    const int*   __restrict__ species,  // (M, A)
    const int*   __restrict__ triu,     // (4, 4)
    float*       __restrict__ out)      // (M, A, 384)
{
    __shared__ float4 satm[AA];   // x,y,z,species(bits)
    __shared__ float4 nA[AA];     // angular nbr: ux,uy,uz,d
    __shared__ float2 nB[AA];     // angular nbr: fc_A, species(bits)
    __shared__ float2 rjp[AA];    // radial nbr: d, 0.25*fc_R
    __shared__ float  rsp[AA];    // radial nbr: species(bits)
    __shared__ int    s_triu[NSPEC * NSPEC];

    const int mi   = blockIdx.x;        // env = (m, i)
    const int m    = mi / AA;
    const int i    = mi % AA;
    const int lane = threadIdx.x;

    // per-lane parameters
    const float etaR   = __ldg(EtaR);
    const float etaA   = __ldg(EtaA);
    const float zeta   = __ldg(Zeta);
    const float shfr_r = __ldg(&ShfR[lane & 15]);
    const float sha    = __ldg(&ShfA[lane >> 3]);
    const float shz    = __ldg(&ShfZ[lane & 7]);
    const float cz = __cosf(shz), sz = __sinf(shz);
    const bool  z32 = (zeta == 32.0f);

    if (lane < NSPEC * NSPEC) s_triu[lane] = triu[lane];
    #pragma unroll
    for (int t = lane; t < AA; t += 32) {
        const float* c = coords + (m * AA + t) * 3;
        satm[t] = make_float4(c[0], c[1], c[2],
                              __int_as_float(species[m * AA + t]));
    }
    __syncwarp();

    const float4 ai  = satm[i];
    const int    spi = __float_as_int(ai.w);

    // ---- distances + warp-ballot compaction (2 iterations cover 48 atoms) ----
    int nAng = 0, nRad = 0;
    #pragma unroll
    for (int it = 0; it < 2; it++) {
        int  j   = lane + it * 32;
        bool has = (j < AA);
        float4 aj = has ? satm[j] : make_float4(0.f, 0.f, 0.f, __int_as_float(-1));
        int  spj = __float_as_int(aj.w);
        float dx = aj.x - ai.x, dy = aj.y - ai.y, dz = aj.z - ai.z;
        float d2 = dx * dx + dy * dy + dz * dz;
        float d  = sqrtf(d2 > 0.0f ? d2 : 1.0f);
        bool pvb = has && (spi >= 0) && (spj >= 0) && (j != i);
        bool inR = pvb && (d <= RCR_F);
        bool inA = pvb && (d <= RCA_F);
        unsigned mR = __ballot_sync(FULLM, inR);
        unsigned mAms = __ballot_sync(FULLM, inA);
        unsigned lt = (1u << lane) - 1u;
        if (inR) {
            int idx = nRad + __popc(mR & lt);
            rjp[idx] = make_float2(d, 0.25f * (0.5f * __cosf(d * (PI_F / RCR_F)) + 0.5f));
            rsp[idx] = aj.w;
        }
        if (inA) {
            int idx = nAng + __popc(mAms & lt);
            float rinv = 1.0f / d;
            nA[idx] = make_float4(dx * rinv, dy * rinv, dz * rinv, d);
            nB[idx] = make_float2(0.5f * __cosf(d * (PI_F / RCA_F)) + 0.5f, aj.w);
        }
        nRad += __popc(mR);
        nAng += __popc(mAms);
    }
    __syncwarp();

    float* ob = out + mi * OUTDIM;

    // ---- radial: register accumulation, 2 j's per iteration ----
    {
        float a0 = 0.f, a1 = 0.f, a2 = 0.f, a3 = 0.f;
        const int half = lane >> 4;
        for (int t = half; t < nRad; t += 2) {
            float2 dp = rjp[t];
            float  u  = dp.x - shfr_r;
            float  v  = dp.y * __expf(-etaR * u * u);
            int    s  = __float_as_int(rsp[t]);
            a0 += (s == 0) ? v : 0.0f;
            a1 += (s == 1) ? v : 0.0f;
            a2 += (s == 2) ? v : 0.0f;
            a3 += (s == 3) ? v : 0.0f;
        }
        a0 += __shfl_xor_sync(FULLM, a0, 16);
        a1 += __shfl_xor_sync(FULLM, a1, 16);
        a2 += __shfl_xor_sync(FULLM, a2, 16);
        a3 += __shfl_xor_sync(FULLM, a3, 16);
        if (lane < 16) {
            ob[0 * NSHFR + lane] = a0;
            ob[1 * NSHFR + lane] = a1;
            ob[2 * NSHFR + lane] = a2;
            ob[3 * NSHFR + lane] = a3;
        }
    }

    // ---- angular: serial pair walk, lanes = 32 channels, register acc ----
    {
        float c0 = 0.f, c1 = 0.f, c2 = 0.f, c3 = 0.f, c4 = 0.f;
        float c5 = 0.f, c6 = 0.f, c7 = 0.f, c8 = 0.f, c9 = 0.f;
        float e0 = 0.f, e1 = 0.f, e2 = 0.f, e3 = 0.f, e4 = 0.f;
        float e5 = 0.f, e6 = 0.f, e7 = 0.f, e8 = 0.f, e9 = 0.f;

        const int n      = nAng;
        const int npairs = (n * (n - 1)) >> 1;
        int jj = 0, kk = 1;

        #define ANG_PAIR(JJ, KK, C0,C1,C2,C3,C4,C5,C6,C7,C8,C9)                     \
        {                                                                            \
            float4 aj = nA[JJ];                                                      \
            float4 ak = nA[KK];                                                      \
            float2 bj = nB[JJ];                                                      \
            float2 bk = nB[KK];                                                      \
            float c = 0.95f * (aj.x * ak.x + aj.y * ak.y + aj.z * ak.z);             \
            c = fminf(0.99f, fmaxf(-0.99f, c));                                      \
            float s = sqrtf(1.0f - c * c);                                           \
            float base = 0.5f + 0.5f * (c * cz + s * sz);                            \
            float f1;                                                                \
            if (z32) {                                                               \
                float b2 = base * base; float b4 = b2 * b2;                          \
                float b8 = b4 * b4; float b16 = b8 * b8; f1 = b16 * b16;             \
            } else { f1 = __powf(base, zeta); }                                      \
            float uu = 0.5f * (aj.w + ak.w) - sha;                                   \
            float f2 = __expf(-etaA * uu * uu);                                      \
            float v  = f1 * f2 * 2.0f * bj.x * bk.x;                                 \
            int p = s_triu[__float_as_int(bj.y) * NSPEC + __float_as_int(bk.y)];     \
            switch (p) {                                                             \
                case 0: C0 += v; break; case 1: C1 += v; break;                      \
                case 2: C2 += v; break; case 3: C3 += v; break;                      \
                case 4: C4 += v; break; case 5: C5 += v; break;                      \
                case 6: C6 += v; break; case 7: C7 += v; break;                      \
                case 8: C8 += v; break; default: C9 += v; break;                     \
            }                                                                        \
        }

        int t = 0;
        for (; t + 1 < npairs; t += 2) {
            int jjA = jj, kkA = kk;
            kk++; if (kk >= n) { jj++; kk = jj + 1; }
            int jjB = jj, kkB = kk;
            kk++; if (kk >= n) { jj++; kk = jj + 1; }
            ANG_PAIR(jjA, kkA, c0,c1,c2,c3,c4,c5,c6,c7,c8,c9);
            ANG_PAIR(jjB, kkB, e0,e1,e2,e3,e4,e5,e6,e7,e8,e9);
        }
        if (t < npairs) {
            ANG_PAIR(jj, kk, c0,c1,c2,c3,c4,c5,c6,c7,c8,c9);
        }
        #undef ANG_PAIR

        float* oa = ob + RADDIM + lane;
        oa[0 * 32] = c0 + e0;  oa[1 * 32] = c1 + e1;
        oa[2 * 32] = c2 + e2;  oa[3 * 32] = c3 + e3;
        oa[4 * 32] = c4 + e4;  oa[5 * 32] = c5 + e5;
        oa[6 * 32] = c6 + e6;  oa[7 * 32] = c7 + e7;
        oa[8 * 32] = c8 + e8;  oa[9 * 32] = c9 + e9;
    }
}

extern "C" void kernel_launch(void* const* d_in, const int* in_sizes, int n_in,
                              void* d_out, int out_size)
{
    const float* coordsp = (const float*)d_in[0];
    const float* etaRp   = (const float*)d_in[1];
    const float* shfRp   = (const float*)d_in[2];
    const float* etaAp   = (const float*)d_in[3];
    const float* zetap   = (const float*)d_in[4];
    const float* shfAp   = (const float*)d_in[5];
    const float* shfZp   = (const float*)d_in[6];
    const int*   specp   = (const int*)d_in[7];
    const int*   triup   = (const int*)d_in[8];
    float*       outp    = (float*)d_out;

    aev_kernel<<<MM * AA, 32>>>(coordsp, etaRp, shfRp, etaAp, zetap, shfAp,
                                shfZp, specp, triup, outp);
}

// round 8
// speedup vs baseline: 2.9566x; 2.9566x over previous
#include <cuda_runtime.h>
#include <math.h>

#define MM      8
#define AA      48
#define NSPEC   4
#define NPAIRCH 10
#define NSHFR   16
#define RADDIM  (NSPEC * NSHFR)            /* 64  */
#define ANGDIM  (NPAIRCH * 32)             /* 320 */
#define OUTDIM  (RADDIM + ANGDIM)          /* 384 */
#define RCR_F   5.2f
#define RCA_F   3.5f
#define PI_F    3.14159265358979323846f
#define NT      512
#define NWARPS  (NT / 32)
#define FULLM   0xffffffffu

__global__ __launch_bounds__(NT, 1) void aev_kernel(
    const float* __restrict__ coords,   // (M, A, 3)
    const float* __restrict__ EtaR,     // (1,)
    const float* __restrict__ ShfR,     // (16,)
    const float* __restrict__ EtaA,     // (1,)
    const float* __restrict__ Zeta,     // (1,)
    const float* __restrict__ ShfA,     // (4,)
    const float* __restrict__ ShfZ,     // (8,)
    const int*   __restrict__ species,  // (M, A)
    const int*   __restrict__ triu,     // (4, 4)
    float*       __restrict__ out)      // (M, A, 384)
{
    __shared__ float4 satm[AA];    // x,y,z,species(bits)
    __shared__ float  sdd[AA];     // d (all j)
    __shared__ float  spre[AA];    // 0.25*fc_R (0 if invalid/out-of-range)
    __shared__ float4 nA[AA];      // angular nbr: ux,uy,uz,d
    __shared__ float2 nB[AA];      // angular nbr: fc_A, species(bits)
    __shared__ int    nnbr;
    __shared__ float  rad[RADDIM];
    __shared__ float  ang[ANGDIM];

    const int mi   = blockIdx.x;        // env = (m, i)
    const int m    = mi / AA;
    const int i    = mi % AA;
    const int tid  = threadIdx.x;
    const int wid  = tid >> 5;
    const int lane = tid & 31;

    // ---- per-lane parameters ----
    const float etaR   = __ldg(EtaR);
    const float etaA   = __ldg(EtaA);
    const float zeta   = __ldg(Zeta);
    const float shfr_r = __ldg(&ShfR[lane & 15]);
    const float sha    = __ldg(&ShfA[lane >> 3]);
    const float shz    = __ldg(&ShfZ[lane & 7]);
    const float cz = __cosf(shz), sz = __sinf(shz);
    const bool  z32 = (zeta == 32.0f);

    // pack the 16 triu entries (each 0..9, fits a nibble) into two u32 regs
    int tv = (lane < NSPEC * NSPEC) ? __ldg(&triu[lane]) : 0;
    unsigned triuLo = 0, triuHi = 0;
    #pragma unroll
    for (int k = 0; k < 8; k++) {
        triuLo |= ((unsigned)__shfl_sync(FULLM, tv, k)     & 15u) << (4 * k);
        triuHi |= ((unsigned)__shfl_sync(FULLM, tv, k + 8) & 15u) << (4 * k);
    }

    // ---- phase 1: stage molecule + zero accumulators ----
    if (tid == 0) nnbr = 0;
    if (tid < AA) {
        const float* c = coords + (m * AA + tid) * 3;
        satm[tid] = make_float4(c[0], c[1], c[2],
                                __int_as_float(species[m * AA + tid]));
    }
    if (tid < OUTDIM) {
        if (tid < RADDIM) rad[tid] = 0.0f;
        else              ang[tid - RADDIM] = 0.0f;
    }
    __syncthreads();

    // ---- phase 2: distances + radial precompute + angular compaction ----
    if (tid < AA) {
        float4 aj = satm[tid];
        float4 ai = satm[i];
        int   spj = __float_as_int(aj.w);
        int   spi = __float_as_int(ai.w);
        float dx = aj.x - ai.x, dy = aj.y - ai.y, dz = aj.z - ai.z;
        float d2 = dx * dx + dy * dy + dz * dz;
        float d  = sqrtf(d2 > 0.0f ? d2 : 1.0f);
        bool pvb = (spi >= 0) && (spj >= 0) && (tid != i);
        float pr = 0.0f;
        if (pvb && d <= RCR_F)
            pr = 0.25f * (0.5f * __cosf(d * (PI_F / RCR_F)) + 0.5f);
        sdd[tid]  = d;
        spre[tid] = pr;
        if (pvb && d <= RCA_F) {
            int   idx  = atomicAdd(&nnbr, 1);
            float rinv = 1.0f / d;
            nA[idx] = make_float4(dx * rinv, dy * rinv, dz * rinv, d);
            nB[idx] = make_float2(0.5f * __cosf(d * (PI_F / RCA_F)) + 0.5f, aj.w);
        }
    }
    __syncthreads();

    // ---- phase 3a: radial — 768 (j, r) items, r == lane&15 by construction ----
    {
        // iteration 0: t = tid (all 512 < 768); iteration 1: t = tid + 512 (tid < 256)
        #pragma unroll
        for (int it = 0; it < 2; it++) {
            int t = tid + it * NT;
            if (t < AA * NSHFR) {
                int   j  = t >> 4;
                float pr = spre[j];
                if (pr != 0.0f) {
                    float u = sdd[j] - shfr_r;
                    int   s = __float_as_int(satm[j].w);
                    atomicAdd(&rad[s * NSHFR + (lane & 15)],
                              pr * __expf(-etaR * u * u));
                }
            }
        }
    }

    // ---- phase 3b: angular — warp-per-pair, closed-form triangular decode ----
    {
        const int n      = nnbr;
        const int npairs = (n * (n - 1)) >> 1;

        for (int t = wid; t < npairs; t += NWARPS) {
            // decode pair t -> (jj, kk), jj < kk < n
            float tn = 2.0f * (float)n - 1.0f;
            int jj = (int)(0.5f * (tn - sqrtf(tn * tn - 8.0f * (float)t)));
            jj = max(0, min(jj, n - 2));
            int start = (jj * (2 * n - jj - 1)) >> 1;
            if (t < start) {
                jj--; start = (jj * (2 * n - jj - 1)) >> 1;
            } else if (t >= start + n - 1 - jj) {
                start += n - 1 - jj; jj++;
            }
            int kk = jj + 1 + (t - start);

            float4 aj = nA[jj];
            float4 ak = nA[kk];
            float2 bj = nB[jj];
            float2 bk = nB[kk];
            float c = 0.95f * (aj.x * ak.x + aj.y * ak.y + aj.z * ak.z);
            c = fminf(0.99f, fmaxf(-0.99f, c));
            float s    = sqrtf(1.0f - c * c);     // sin(arccos(c)) >= 0
            float davg = 0.5f * (aj.w + ak.w);
            float fcp2 = 2.0f * bj.x * bk.x;

            // channel from packed nibble table (no LDS in the chain)
            int idx = __float_as_int(bj.y) * NSPEC + __float_as_int(bk.y);
            unsigned sel = (idx < 8) ? triuLo : triuHi;
            int p = (sel >> ((idx & 7) * 4)) & 15;

            // cos(theta - ShfZ) = c*cosZ + sin(theta)*sinZ
            float base = 0.5f + 0.5f * (c * cz + s * sz);
            float f1;
            if (z32) {
                float b2 = base * base;
                float b4 = b2 * b2;
                float b8 = b4 * b4;
                float b16 = b8 * b8;
                f1 = b16 * b16;
            } else {
                f1 = __powf(base, zeta);
            }
            float uu = davg - sha;
            float f2 = __expf(-etaA * uu * uu);
            atomicAdd(&ang[p * 32 + lane], f1 * f2 * fcp2);
        }
    }
    __syncthreads();

    // ---- phase 4: write out (single pass, 512 >= 384) ----
    if (tid < OUTDIM) {
        float v = (tid < RADDIM) ? rad[tid] : ang[tid - RADDIM];
        out[mi * OUTDIM + tid] = v;
    }
}

extern "C" void kernel_launch(void* const* d_in, const int* in_sizes, int n_in,
                              void* d_out, int out_size)
{
    const float* coordsp = (const float*)d_in[0];
    const float* etaRp   = (const float*)d_in[1];
    const float* shfRp   = (const float*)d_in[2];
    const float* etaAp   = (const float*)d_in[3];
    const float* zetap   = (const float*)d_in[4];
    const float* shfAp   = (const float*)d_in[5];
    const float* shfZp   = (const float*)d_in[6];
    const int*   specp   = (const int*)d_in[7];
    const int*   triup   = (const int*)d_in[8];
    float*       outp    = (float*)d_out;

    aev_kernel<<<MM * AA, NT>>>(coordsp, etaRp, shfRp, etaAp, zetap, shfAp,
                                shfZp, specp, triup, outp);
}

// round 9
// speedup vs baseline: 3.9673x; 1.3418x over previous
#include <cuda_runtime.h>
#include <math.h>

#define MM      8
#define AA      48
#define NSPEC   4
#define NPAIRCH 10
#define NSHFR   16
#define RADDIM  (NSPEC * NSHFR)            /* 64  */
#define ANGDIM  (NPAIRCH * 32)             /* 320 */
#define OUTDIM  (RADDIM + ANGDIM)          /* 384 */
#define RCR_F   5.2f
#define RCA_F   3.5f
#define PI_F    3.14159265358979323846f
#define NT      512
#define NWARPS  (NT / 32)
#define MAXPAIR ((AA * (AA - 1)) / 2)      /* 1128 */
#define FULLM   0xffffffffu

__global__ __launch_bounds__(NT, 1) void aev_kernel(
    const float* __restrict__ coords,   // (M, A, 3)
    const float* __restrict__ EtaR,     // (1,)
    const float* __restrict__ ShfR,     // (16,)
    const float* __restrict__ EtaA,     // (1,)
    const float* __restrict__ Zeta,     // (1,)
    const float* __restrict__ ShfA,     // (4,)
    const float* __restrict__ ShfZ,     // (8,)
    const int*   __restrict__ species,  // (M, A)
    const int*   __restrict__ triu,     // (4, 4)
    float*       __restrict__ out)      // (M, A, 384)
{
    __shared__ float4 satm[AA];    // x,y,z,species(bits)
    __shared__ float  sdd[AA];     // d (all j)
    __shared__ float  spre[AA];    // 0.25*fc_R (0 if invalid/out-of-range)
    __shared__ float4 nA[AA];      // angular nbr: ux,uy,uz,d
    __shared__ float2 nB[AA];      // angular nbr: fc_A, species(bits)
    __shared__ float4 pairdata[MAXPAIR];        // {cos, sin, davg, 2fcfc}
    __shared__ unsigned char pairp[MAXPAIR];    // channel 0..9
    __shared__ int    nnbr;
    __shared__ float  rad[RADDIM];
    __shared__ float  ang[ANGDIM];

    const int mi   = blockIdx.x;        // env = (m, i)
    const int m    = mi / AA;
    const int i    = mi % AA;
    const int tid  = threadIdx.x;
    const int wid  = tid >> 5;
    const int lane = tid & 31;

    // ---- per-lane parameters ----
    const float etaR   = __ldg(EtaR);
    const float etaA   = __ldg(EtaA);
    const float zeta   = __ldg(Zeta);
    const float shfr_r = __ldg(&ShfR[lane & 15]);
    const float sha    = __ldg(&ShfA[lane >> 3]);
    const float shz    = __ldg(&ShfZ[lane & 7]);
    const float cz = __cosf(shz), sz = __sinf(shz);
    const bool  z32 = (zeta == 32.0f);

    // pack the 16 triu entries (each 0..9 -> nibble) into two u32 regs
    int tv = (lane < NSPEC * NSPEC) ? __ldg(&triu[lane]) : 0;
    unsigned triuLo = 0, triuHi = 0;
    #pragma unroll
    for (int k = 0; k < 8; k++) {
        triuLo |= ((unsigned)__shfl_sync(FULLM, tv, k)     & 15u) << (4 * k);
        triuHi |= ((unsigned)__shfl_sync(FULLM, tv, k + 8) & 15u) << (4 * k);
    }

    // ---- phase 1: stage molecule + zero accumulators ----
    if (tid == 0) nnbr = 0;
    if (tid < AA) {
        const float* c = coords + (m * AA + tid) * 3;
        satm[tid] = make_float4(c[0], c[1], c[2],
                                __int_as_float(species[m * AA + tid]));
    }
    if (tid < OUTDIM) {
        if (tid < RADDIM) rad[tid] = 0.0f;
        else              ang[tid - RADDIM] = 0.0f;
    }
    __syncthreads();

    // ---- phase 2: distances + radial precompute + angular compaction ----
    if (tid < AA) {
        float4 aj = satm[tid];
        float4 ai = satm[i];
        int   spj = __float_as_int(aj.w);
        int   spi = __float_as_int(ai.w);
        float dx = aj.x - ai.x, dy = aj.y - ai.y, dz = aj.z - ai.z;
        float d2 = dx * dx + dy * dy + dz * dz;
        float d  = sqrtf(d2 > 0.0f ? d2 : 1.0f);
        bool pvb = (spi >= 0) && (spj >= 0) && (tid != i);
        float pr = 0.0f;
        if (pvb && d <= RCR_F)
            pr = 0.25f * (0.5f * __cosf(d * (PI_F / RCR_F)) + 0.5f);
        sdd[tid]  = d;
        spre[tid] = pr;
        if (pvb && d <= RCA_F) {
            int   idx  = atomicAdd(&nnbr, 1);
            float rinv = 1.0f / d;
            nA[idx] = make_float4(dx * rinv, dy * rinv, dz * rinv, d);
            nB[idx] = make_float2(0.5f * __cosf(d * (PI_F / RCA_F)) + 0.5f, aj.w);
        }
    }
    __syncthreads();

    const int n      = nnbr;
    const int npairs = (n * (n - 1)) >> 1;

    // ---- phase 3a: radial — 768 (j, r) items, r == lane&15 by construction ----
    #pragma unroll
    for (int it = 0; it < 2; it++) {
        int t = tid + it * NT;
        if (t < AA * NSHFR) {
            int   j  = t >> 4;
            float pr = spre[j];
            if (pr != 0.0f) {
                float u = sdd[j] - shfr_r;
                int   s = __float_as_int(satm[j].w);
                atomicAdd(&rad[s * NSHFR + (lane & 15)],
                          pr * __expf(-etaR * u * u));
            }
        }
    }

    // ---- phase 3b: pair precompute — thread-per-pair, closed-form decode ----
    for (int t = tid; t < npairs; t += NT) {
        float tn = 2.0f * (float)n - 1.0f;
        int jj = (int)(0.5f * (tn - sqrtf(tn * tn - 8.0f * (float)t)));
        jj = max(0, min(jj, n - 2));
        int start = (jj * (2 * n - jj - 1)) >> 1;
        if (t < start) {
            jj--; start = (jj * (2 * n - jj - 1)) >> 1;
        } else if (t >= start + n - 1 - jj) {
            start += n - 1 - jj; jj++;
        }
        int kk = jj + 1 + (t - start);

        float4 aj = nA[jj];
        float4 ak = nA[kk];
        float2 bj = nB[jj];
        float2 bk = nB[kk];
        float c = 0.95f * (aj.x * ak.x + aj.y * ak.y + aj.z * ak.z);
        c = fminf(0.99f, fmaxf(-0.99f, c));
        float4 pd;
        pd.x = c;
        pd.y = sqrtf(1.0f - c * c);            // sin(arccos(c)) >= 0
        pd.z = 0.5f * (aj.w + ak.w);           // davg
        pd.w = 2.0f * bj.x * bk.x;             // 2*fcj*fck
        pairdata[t] = pd;

        int idx = __float_as_int(bj.y) * NSPEC + __float_as_int(bk.y);
        unsigned sel = (idx < 8) ? triuLo : triuHi;
        pairp[t] = (unsigned char)((sel >> ((idx & 7) * 4)) & 15);
    }
    __syncthreads();

    // ---- phase 4: radial write (overlaps) + angular lean consumer loop ----
    if (tid < RADDIM) out[mi * OUTDIM + tid] = rad[tid];

    {
        #pragma unroll 2
        for (int t = wid; t < npairs; t += NWARPS) {
            float4 pd = pairdata[t];           // LDS.128 broadcast
            int    p  = pairp[t];              // LDS.U8 broadcast
            // cos(theta - ShfZ) = c*cosZ + sin(theta)*sinZ
            float base = 0.5f + 0.5f * (pd.x * cz + pd.y * sz);
            float f1;
            if (z32) {
                float b2 = base * base;
                float b4 = b2 * b2;
                float b8 = b4 * b4;
                float b16 = b8 * b8;
                f1 = b16 * b16;
            } else {
                f1 = __powf(base, zeta);
            }
            float uu = pd.z - sha;
            float f2 = __expf(-etaA * uu * uu);
            atomicAdd(&ang[p * 32 + lane], f1 * f2 * pd.w);
        }
    }
    __syncthreads();

    // ---- phase 5: angular write ----
    if (tid < ANGDIM)
        out[mi * OUTDIM + RADDIM + tid] = ang[tid];
}

extern "C" void kernel_launch(void* const* d_in, const int* in_sizes, int n_in,
                              void* d_out, int out_size)
{
    const float* coordsp = (const float*)d_in[0];
    const float* etaRp   = (const float*)d_in[1];
    const float* shfRp   = (const float*)d_in[2];
    const float* etaAp   = (const float*)d_in[3];
    const float* zetap   = (const float*)d_in[4];
    const float* shfAp   = (const float*)d_in[5];
    const float* shfZp   = (const float*)d_in[6];
    const int*   specp   = (const int*)d_in[7];
    const int*   triup   = (const int*)d_in[8];
    float*       outp    = (float*)d_out;

    aev_kernel<<<MM * AA, NT>>>(coordsp, etaRp, shfRp, etaAp, zetap, shfAp,
                                shfZp, specp, triup, outp);
}